// round 4
// baseline (speedup 1.0000x reference)
#include <cuda_runtime.h>
#include <math.h>
#include <stdint.h>

#define N_FEAT 7
#define FUZZ   2187
#define MID    512
#define NCLS   10
#define BATCH  4096
#define T21    21
#define CHUNK_K 9
#define NCHUNK  243            // 243*9 = 2187 k's
#define NSLOT   11             // f0..f4 (5) + f5 (3) + f6 (3)
#define SLICE_BYTES 61236      // 7*2187*4 bytes per k-slice
#define NVEC    3828           // 61248/16 aligned vectors per slice
#define BUFB    61440          // padded smem buffer bytes per stage
#define K1_THREADS 768
#define WEI_BYTES ((size_t)15309 * 2187 * 4)

// ---- device scratch (no allocations allowed) ----
__device__ float g_p[(size_t)NCHUNK * NSLOT * FUZZ];   // 23.4 MB partials
__device__ float g_S[T21 * FUZZ];
__device__ float g_rowS[T21];
__device__ float g_W23[NCLS * MID];
__device__ float g_G[NCLS * T21];
__device__ float g_q[NCLS];
__device__ float g_cc2[NCLS];

__device__ __forceinline__ void cpasync16(uint32_t saddr, const void* gaddr) {
    asm volatile("cp.async.cg.shared.global [%0], [%1], 16;\n"
                 :: "r"(saddr), "l"(gaddr) : "memory");
}

// ============================================================
// K1: SMEM-staged wei reduction into compact partials.
//   block = chunk of 9 k's; copies each 61KB k-slice via cp.async
//   (double-buffered), accumulates 11 slots x 3 column strips.
// ============================================================
__global__ void __launch_bounds__(K1_THREADS) k_stage1(const float* __restrict__ wei) {
    extern __shared__ char sm[];
    uint32_t smb;
    { uint64_t t64; asm("cvta.to.shared.u64 %0, %1;" : "=l"(t64) : "l"(sm)); smb = (uint32_t)t64; }

    int tid   = threadIdx.x;
    int chunk = blockIdx.x;
    const char* wc = (const char*)wei;

    float acc[NSLOT][3];
#pragma unroll
    for (int s = 0; s < NSLOT; s++)
#pragma unroll
        for (int st = 0; st < 3; st++) acc[s][st] = 0.f;

    int jv0 = tid, jv1 = tid + K1_THREADS, jv2 = tid + 2 * K1_THREADS;
    bool j2ok = (jv2 < FUZZ);
    int jr2 = j2ok ? jv2 : (FUZZ - 1);

    // ---- copy helper (inlined via lambda-like macro) ----
#define COPY_SLICE(K, BUFIDX) do {                                          \
        size_t gbase = (size_t)(K) * SLICE_BYTES;                           \
        size_t a0 = gbase & ~(size_t)15;                                    \
        uint32_t sb = smb + (BUFIDX) * BUFB;                                \
        for (int v = tid; v < NVEC; v += K1_THREADS) {                      \
            size_t g = a0 + ((size_t)v << 4);                               \
            if (g + 16 <= WEI_BYTES) {                                      \
                cpasync16(sb + ((uint32_t)v << 4), wc + g);                 \
            } else {                                                        \
                float* d = (float*)(sm + (BUFIDX) * BUFB + (v << 4));       \
                for (int bb = 0; bb < 4; bb++) {                            \
                    size_t gb = g + 4u * bb;                                \
                    d[bb] = (gb + 4 <= WEI_BYTES) ? *(const float*)(wc + gb) : 0.f; \
                }                                                           \
            }                                                               \
        }                                                                   \
        asm volatile("cp.async.commit_group;" ::: "memory");                \
    } while (0)

    COPY_SLICE(chunk * CHUNK_K, 0);

#pragma unroll
    for (int q = 0; q < CHUNK_K; q++) {
        if (q < CHUNK_K - 1) COPY_SLICE(chunk * CHUNK_K + q + 1, (q + 1) & 1);
        if (q < CHUNK_K - 1) asm volatile("cp.async.wait_group 1;" ::: "memory");
        else                 asm volatile("cp.async.wait_group 0;" ::: "memory");
        __syncthreads();

        size_t gbase = (size_t)(chunk * CHUNK_K + q) * SLICE_BYTES;
        int shift = (int)(gbase & 15);
        const float* base = (const float*)(sm + (q & 1) * BUFB + shift);
#pragma unroll
        for (int f = 0; f < 7; f++) {
            int slot = (f < 5) ? f : ((f == 5) ? (5 + q / 3) : (8 + q % 3));
            const float* rowp = base + f * FUZZ;
            acc[slot][0] += rowp[jv0];
            acc[slot][1] += rowp[jv1];
            acc[slot][2] += rowp[jr2];
        }
        __syncthreads();
    }
#undef COPY_SLICE

    float* gp = g_p + (size_t)chunk * NSLOT * FUZZ;
#pragma unroll
    for (int slot = 0; slot < NSLOT; slot++) {
        gp[slot * FUZZ + jv0] = acc[slot][0];
        gp[slot * FUZZ + jv1] = acc[slot][1];
        if (j2ok) gp[slot * FUZZ + jv2] = acc[slot][2];
    }
}

// ============================================================
// K2: reduce partials -> S (fixed order) ; W23 = W3 @ W2
// ============================================================
__global__ void __launch_bounds__(256) k_reduce(const float* __restrict__ W2,
                                                const float* __restrict__ W3) {
    int b = blockIdx.x, tid = threadIdx.x;
    if (b < 180) {
        int idx = b * 256 + tid;
        if (idx >= T21 * FUZZ) return;
        int t = idx / FUZZ, j = idx % FUZZ;
        int f = t / 3, m = t % 3;
        float s = 0.f;
        if (f < 5) {
            const int Dt[5] = {81, 27, 9, 3, 1};
            int D = Dt[f];
            int n3D = 3 * D;
            for (int hi = 0; hi < NCHUNK / n3D; hi++)
                for (int lo = 0; lo < D; lo++) {
                    int c = hi * n3D + m * D + lo;
                    s += g_p[((size_t)c * NSLOT + f) * FUZZ + j];
                }
        } else {
            int slot = (f == 5) ? (5 + m) : (8 + m);
            const float* p = g_p + (size_t)slot * FUZZ + j;
#pragma unroll 3
            for (int c = 0; c < NCHUNK; c++)
                s += p[(size_t)c * NSLOT * FUZZ];
        }
        g_S[t * FUZZ + j] = s;
    } else {
        // W23[n][i] = sum_j W3[n][j] * W2[j][i]
        int bb = b - 180;             // 0..19
        int n = bb >> 1, half = bb & 1;
        int i = half * 256 + tid;
        float a = 0.f;
        const float* w3 = W3 + n * FUZZ;
#pragma unroll 4
        for (int j = 0; j < FUZZ; j++)
            a += __ldg(w3 + j) * __ldg(W2 + (size_t)j * MID + i);
        g_W23[n * MID + i] = a;
    }
}

// ============================================================
// K3: per-n fold. V[j] = W3[n][j] + sum_i W23[n][i] W1[i][j]
//     G[n][t] = sum_j V[j] S[t][j] ; q[n] = sum_j V[j]
//     cc2[n] = sum_j W3[n][j] b2[j] + b3[n] + sum_i W23[n][i] b1[i]
//     block 10: rowS[t] = sum_j S[t][j]
// ============================================================
__global__ void __launch_bounds__(672) k_fold(const float* __restrict__ W1,
                                              const float* __restrict__ W3,
                                              const float* __restrict__ b1,
                                              const float* __restrict__ b2,
                                              const float* __restrict__ b3) {
    __shared__ float sW[MID];
    __shared__ float sV[FUZZ];
    __shared__ float sred[21];
    int b = blockIdx.x, tid = threadIdx.x, lane = tid & 31, w = tid >> 5;

    if (b < NCLS) {
        int n = b;
        if (tid < MID) sW[tid] = g_W23[n * MID + tid];
        __syncthreads();

        for (int st = 0; st < 4; st++) {
            int j = st * 672 + tid;
            if (j < FUZZ) {
                float a = __ldg(W3 + n * FUZZ + j);
                const float* wp = W1 + j;
#pragma unroll 8
                for (int i = 0; i < MID; i++)
                    a += sW[i] * __ldg(wp + (size_t)i * FUZZ);
                sV[j] = a;
            }
        }
        __syncthreads();

        // G[n][t], warp per t (exactly 21 warps)
        {
            int t = w;
            float a = 0.f;
            const float* Sp = g_S + t * FUZZ;
            for (int j = lane; j < FUZZ; j += 32)
                a += sV[j] * __ldg(Sp + j);
            for (int o = 16; o; o >>= 1) a += __shfl_down_sync(0xffffffffu, a, o);
            if (lane == 0) g_G[n * T21 + t] = a;
        }

        // q[n] = sum_j V[j]
        float p = 0.f;
        for (int j = tid; j < FUZZ; j += 672) p += sV[j];
        for (int o = 16; o; o >>= 1) p += __shfl_down_sync(0xffffffffu, p, o);
        if (lane == 0) sred[w] = p;
        __syncthreads();
        if (tid == 0) {
            float s = 0.f;
#pragma unroll
            for (int k = 0; k < 21; k++) s += sred[k];
            g_q[n] = s;
        }
        __syncthreads();

        // cc2[n]
        float cp = 0.f;
        for (int j = tid; j < FUZZ; j += 672)
            cp += __ldg(W3 + n * FUZZ + j) * __ldg(b2 + j);
        for (int i = tid; i < MID; i += 672)
            cp += sW[i] * __ldg(b1 + i);
        for (int o = 16; o; o >>= 1) cp += __shfl_down_sync(0xffffffffu, cp, o);
        if (lane == 0) sred[w] = cp;
        __syncthreads();
        if (tid == 0) {
            float s = 0.f;
#pragma unroll
            for (int k = 0; k < 21; k++) s += sred[k];
            g_cc2[n] = s + __ldg(b3 + n);
        }
    } else {
        // rowS: warp per t
        int t = w;
        float s = 0.f;
        const float* Sp = g_S + t * FUZZ;
        for (int j = lane; j < FUZZ; j += 32) s += __ldg(Sp + j);
        for (int o = 16; o; o >>= 1) s += __shfl_down_sync(0xffffffffu, s, o);
        if (lane == 0) g_rowS[t] = s;
    }
}

// ============================================================
// K4: one thread per batch row (~250 FMA + 21 exp each)
// ============================================================
__global__ void __launch_bounds__(256) k_main(
        const float* __restrict__ x,  const float* __restrict__ cc,
        const float* __restrict__ bb, const float* __restrict__ bais,
        float* __restrict__ out) {
    __shared__ float sG[NCLS * T21];
    __shared__ float sq[NCLS];
    __shared__ float scc[NCLS];
    __shared__ float srowS[T21];
    __shared__ float sc[T21];
    __shared__ float sib[T21];

    int tid = threadIdx.x;
    for (int e = tid; e < NCLS * T21; e += 256) sG[e] = g_G[e];
    if (tid < NCLS) { sq[tid] = g_q[tid]; scc[tid] = g_cc2[tid]; }
    if (tid < T21) {
        srowS[tid] = g_rowS[tid];
        sc[tid] = __ldg(cc + tid);
        float bw = __ldg(bb + tid);
        sib[tid] = 1.0f / (bw * bw);
    }
    float bv = __ldg(bais);
    __syncthreads();

    int row = blockIdx.x * 256 + tid;
    float xv[N_FEAT];
#pragma unroll
    for (int f = 0; f < N_FEAT; f++) xv[f] = __ldg(x + row * N_FEAT + f);

    float u[T21];
    float rs = (float)FUZZ * bv;
#pragma unroll
    for (int t = 0; t < T21; t++) {
        float d = xv[t / 3] - sc[t];
        u[t] = expf(-d * d * sib[t]);
        rs += u[t] * srowS[t];
    }
    float inv = 1.0f / rs;

#pragma unroll
    for (int n = 0; n < NCLS; n++) {
        float s = bv * sq[n];
#pragma unroll
        for (int t = 0; t < T21; t++) s += u[t] * sG[n * T21 + t];
        float h = inv * s + scc[n];
        out[row * NCLS + n] = (h >= 0.f) ? h : 0.2f * h;
    }
}

// ============================================================
extern "C" void kernel_launch(void* const* d_in, const int* in_sizes, int n_in,
                              void* d_out, int out_size) {
    const float* x    = (const float*)d_in[0];
    const float* c    = (const float*)d_in[1];
    const float* b    = (const float*)d_in[2];
    const float* wei  = (const float*)d_in[3];
    const float* bais = (const float*)d_in[4];
    const float* W1   = (const float*)d_in[5];
    const float* b1   = (const float*)d_in[6];
    const float* W2   = (const float*)d_in[7];
    const float* b2   = (const float*)d_in[8];
    const float* W3   = (const float*)d_in[9];
    const float* b3   = (const float*)d_in[10];
    float* out = (float*)d_out;

    // dynamic smem for the double-buffered staging kernel (122,880 B)
    cudaFuncSetAttribute(k_stage1, cudaFuncAttributeMaxDynamicSharedMemorySize, 2 * BUFB);

    k_stage1<<<NCHUNK, K1_THREADS, 2 * BUFB>>>(wei);
    k_reduce<<<200, 256>>>(W2, W3);
    k_fold<<<NCLS + 1, 672>>>(W1, W3, b1, b2, b3);
    k_main<<<BATCH / 256, 256>>>(x, c, b, bais, out);
}

// round 5
// speedup vs baseline: 3.2406x; 3.2406x over previous
#include <cuda_runtime.h>
#include <math.h>

#define N_FEAT 7
#define FUZZ   2187
#define MID    512
#define NCLS   10
#define BATCH  4096
#define T21    21
#define NCHUNK 81          // chunks of 27 k each
#define CHUNK_K 27
#define COLT   9           // column tiles of 256
#define NSLOT  13          // f0..f3 scalar + 3x3 for f4..f6
#define WCH    16          // j-chunks for W23 partials

// ---- device scratch (no allocations allowed) ----
__device__ float g_p[(size_t)NCHUNK * NSLOT * FUZZ];   // 9.2 MB compact partials
__device__ float g_S[T21 * FUZZ];
__device__ float g_rowS[T21];
__device__ float g_T1[T21 * MID];
__device__ float g_r1[MID];
__device__ float g_T3[NCLS * T21];
__device__ float g_r3[NCLS];
__device__ float g_c3[NCLS];
__device__ float g_partW[WCH * NCLS * MID];
__device__ float g_W23[NCLS * MID];

// ============================================================
// Stage 1: compact S partials + W23 partials.
//   k = chunk*27 + kk.  digits f0..f3 are block-constant ->
//   4 scalar accumulators; f4..f6 via predicated 3-way adds.
// ============================================================
__global__ void k_stage1(const float* __restrict__ wei,
                         const float* __restrict__ W2,
                         const float* __restrict__ W3) {
    int b   = blockIdx.x;
    int tid = threadIdx.x;

    if (b < NCHUNK * COLT) {
        int colTile = b % COLT;
        int chunk   = b / COLT;
        int j  = colTile * 256 + tid;
        bool ok = (j < FUZZ);
        int jj = ok ? j : 0;

        float a0 = 0.f, a1 = 0.f, a2 = 0.f, a3 = 0.f;
        float a4[3] = {0.f, 0.f, 0.f};
        float a5[3] = {0.f, 0.f, 0.f};
        float a6[3] = {0.f, 0.f, 0.f};

        const float* base = wei + (size_t)chunk * CHUNK_K * 7 * FUZZ + jj;
#pragma unroll 3
        for (int kk = 0; kk < CHUNK_K; kk++) {
            const float* rp = base + (size_t)kk * 7 * FUZZ;
            a0 += __ldg(rp);
            a1 += __ldg(rp + 1 * FUZZ);
            a2 += __ldg(rp + 2 * FUZZ);
            a3 += __ldg(rp + 3 * FUZZ);
            float v4 = __ldg(rp + 4 * FUZZ);
            float v5 = __ldg(rp + 5 * FUZZ);
            float v6 = __ldg(rp + 6 * FUZZ);
            int m4 = kk / 9, m5 = (kk / 3) % 3, m6 = kk % 3;
            a4[0] += (m4 == 0) ? v4 : 0.f;
            a4[1] += (m4 == 1) ? v4 : 0.f;
            a4[2] += (m4 == 2) ? v4 : 0.f;
            a5[0] += (m5 == 0) ? v5 : 0.f;
            a5[1] += (m5 == 1) ? v5 : 0.f;
            a5[2] += (m5 == 2) ? v5 : 0.f;
            a6[0] += (m6 == 0) ? v6 : 0.f;
            a6[1] += (m6 == 1) ? v6 : 0.f;
            a6[2] += (m6 == 2) ? v6 : 0.f;
        }
        if (ok) {
            float* dst = g_p + (size_t)chunk * (NSLOT * FUZZ) + j;
            dst[0 * FUZZ] = a0;
            dst[1 * FUZZ] = a1;
            dst[2 * FUZZ] = a2;
            dst[3 * FUZZ] = a3;
#pragma unroll
            for (int m = 0; m < 3; m++) {
                dst[(4 + m)  * FUZZ] = a4[m];
                dst[(7 + m)  * FUZZ] = a5[m];
                dst[(10 + m) * FUZZ] = a6[m];
            }
        }
    } else {
        // ---- W23 partial: W23[n,i] = sum_j W3[n,j] * W2[j,i] ----
        int b2    = b - NCHUNK * COLT;
        int itile = b2 & 1;
        int chunk = b2 >> 1;
        int i  = itile * 256 + tid;
        int j0 = chunk * 137;
        int j1 = min(FUZZ, j0 + 137);

        float acc[NCLS];
#pragma unroll
        for (int n = 0; n < NCLS; n++) acc[n] = 0.f;

        for (int j = j0; j < j1; j++) {
            float w2 = __ldg(W2 + j * MID + i);
#pragma unroll
            for (int n = 0; n < NCLS; n++)
                acc[n] += __ldg(W3 + n * FUZZ + j) * w2;
        }
#pragma unroll
        for (int n = 0; n < NCLS; n++)
            g_partW[chunk * (NCLS * MID) + n * MID + i] = acc[n];
    }
}

// ============================================================
// Stage 2: reduce compact partials -> S ; finalize W23
//   t = f*3+m.  f<4: chunks whose digit_f == m, slot f.
//               f>=4: all chunks, slot 4+(f-4)*3+m.
// ============================================================
__global__ void k_reduceS() {
    int b = blockIdx.x, tid = threadIdx.x;
    if (b < 180) {
        int idx = b * 256 + tid;
        if (idx >= T21 * FUZZ) return;
        int t = idx / FUZZ, j = idx % FUZZ;
        int f = t / 3, m = t % 3;

        float s = 0.f;
        if (f < 4) {
            const int Dt[4] = {27, 9, 3, 1};
            int D = Dt[f];
            int n3D = 3 * D;
            for (int hi = 0; hi < NCHUNK / n3D; hi++)
                for (int lo = 0; lo < D; lo++) {
                    int c = hi * n3D + m * D + lo;
                    s += g_p[((size_t)c * NSLOT + f) * FUZZ + j];
                }
        } else {
            int slot = 4 + (f - 4) * 3 + m;
            const float* p = g_p + (size_t)slot * FUZZ + j;
#pragma unroll 3
            for (int c = 0; c < NCHUNK; c++)
                s += p[(size_t)c * NSLOT * FUZZ];
        }
        g_S[t * FUZZ + j] = s;
    } else {
        int e = (b - 180) * 256 + tid;   // 0..5119
        float s = 0.f;
#pragma unroll
        for (int c = 0; c < WCH; c++) s += g_partW[c * (NCLS * MID) + e];
        g_W23[e] = s;
    }
}

// ============================================================
// Stage 3: T1/r1 (warp-per-i), T3/r3/c3, rowS
// ============================================================
__global__ void __launch_bounds__(256) k_stage3(
        const float* __restrict__ W1,
        const float* __restrict__ W3,
        const float* __restrict__ b2) {
    __shared__ float sm[23 * 8];
    int b    = blockIdx.x;
    int tid  = threadIdx.x;
    int lane = tid & 31;
    int warp = tid >> 5;

    if (b < MID / 8) {
        int i = b * 8 + warp;
        float acc[22];
#pragma unroll
        for (int t = 0; t < 22; t++) acc[t] = 0.f;
        for (int j = lane; j < FUZZ; j += 32) {
            float w = __ldg(W1 + i * FUZZ + j);
#pragma unroll
            for (int t = 0; t < T21; t++) acc[t] += w * __ldg(&g_S[t * FUZZ + j]);
            acc[21] += w;
        }
#pragma unroll
        for (int t = 0; t < 22; t++)
            for (int off = 16; off; off >>= 1)
                acc[t] += __shfl_down_sync(0xffffffffu, acc[t], off);
        if (lane == 0) {
#pragma unroll
            for (int t = 0; t < T21; t++) g_T1[t * MID + i] = acc[t];
            g_r1[i] = acc[21];
        }
    } else if (b < MID / 8 + NCLS) {
        int n = b - MID / 8;
        float acc[23];
#pragma unroll
        for (int t = 0; t < 23; t++) acc[t] = 0.f;
        for (int j = tid; j < FUZZ; j += 256) {
            float w3 = __ldg(W3 + n * FUZZ + j);
#pragma unroll
            for (int t = 0; t < T21; t++) acc[t] += w3 * g_S[t * FUZZ + j];
            acc[21] += w3;
            acc[22] += w3 * __ldg(b2 + j);
        }
#pragma unroll
        for (int t = 0; t < 23; t++) {
            for (int off = 16; off; off >>= 1)
                acc[t] += __shfl_down_sync(0xffffffffu, acc[t], off);
            if (lane == 0) sm[t * 8 + warp] = acc[t];
        }
        __syncthreads();
        if (tid < 23) {
            float s = 0.f;
#pragma unroll
            for (int w = 0; w < 8; w++) s += sm[tid * 8 + w];
            if (tid < T21)       g_T3[n * T21 + tid] = s;
            else if (tid == 21)  g_r3[n] = s;
            else                 g_c3[n] = s;
        }
    } else {
        // rowS: warps loop over t
        for (int t = warp; t < T21; t += 8) {
            float s = 0.f;
            const float* Sp = g_S + t * FUZZ;
            for (int j = lane; j < FUZZ; j += 32) s += __ldg(Sp + j);
            for (int off = 16; off; off >>= 1)
                s += __shfl_down_sync(0xffffffffu, s, off);
            if (lane == 0) g_rowS[t] = s;
        }
    }
}

// ============================================================
// Stage 4: fold MID out in-block (230 warp dots), then batch rows
// ============================================================
__global__ void __launch_bounds__(256) k_main(
        const float* __restrict__ x,  const float* __restrict__ cc,
        const float* __restrict__ bb, const float* __restrict__ bais,
        const float* __restrict__ b1, const float* __restrict__ b3,
        float* __restrict__ out) {
    __shared__ float sG[NCLS * T21];
    __shared__ float sq[NCLS];
    __shared__ float scc[NCLS];
    __shared__ float srowS[T21];
    __shared__ float sc[T21];
    __shared__ float sib[T21];

    int tid  = threadIdx.x;
    int lane = tid & 31;
    int warp = tid >> 5;

    // --- prep: G = T3 + W23*T1^T, q = r3 + W23*r1, cc2 = c3+b3+W23*b1 ---
    for (int d = warp; d < NCLS * T21 + 2 * NCLS; d += 8) {
        float s = 0.f;
        if (d < NCLS * T21) {
            int n = d / T21, t = d % T21;
            const float* wp = g_W23 + n * MID;
            const float* tp = g_T1 + t * MID;
#pragma unroll
            for (int k = 0; k < MID / 32; k++)
                s += __ldg(wp + k * 32 + lane) * __ldg(tp + k * 32 + lane);
            for (int o = 16; o; o >>= 1) s += __shfl_down_sync(0xffffffffu, s, o);
            if (lane == 0) sG[d] = s + g_T3[d];
        } else if (d < NCLS * T21 + NCLS) {
            int n = d - NCLS * T21;
            const float* wp = g_W23 + n * MID;
#pragma unroll
            for (int k = 0; k < MID / 32; k++)
                s += __ldg(wp + k * 32 + lane) * __ldg(&g_r1[k * 32 + lane]);
            for (int o = 16; o; o >>= 1) s += __shfl_down_sync(0xffffffffu, s, o);
            if (lane == 0) sq[n] = s + g_r3[n];
        } else {
            int n = d - NCLS * T21 - NCLS;
            const float* wp = g_W23 + n * MID;
#pragma unroll
            for (int k = 0; k < MID / 32; k++)
                s += __ldg(wp + k * 32 + lane) * __ldg(b1 + k * 32 + lane);
            for (int o = 16; o; o >>= 1) s += __shfl_down_sync(0xffffffffu, s, o);
            if (lane == 0) scc[n] = s + g_c3[n] + __ldg(b3 + n);
        }
    }
    if (tid < T21) {
        srowS[tid] = g_rowS[tid];
        sc[tid] = __ldg(cc + tid);
        float bw = __ldg(bb + tid);
        sib[tid] = 1.0f / (bw * bw);
    }
    float bv = __ldg(bais);
    __syncthreads();

    // --- batch rows: one thread per row ---
    int row = blockIdx.x * 256 + tid;
    float xv[N_FEAT];
#pragma unroll
    for (int f = 0; f < N_FEAT; f++) xv[f] = __ldg(x + row * N_FEAT + f);

    float u[T21];
    float rs = (float)FUZZ * bv;
#pragma unroll
    for (int t = 0; t < T21; t++) {
        float d = xv[t / 3] - sc[t];
        u[t] = expf(-d * d * sib[t]);
        rs += u[t] * srowS[t];
    }
    float inv = 1.0f / rs;

#pragma unroll
    for (int n = 0; n < NCLS; n++) {
        float s = bv * sq[n];
#pragma unroll
        for (int t = 0; t < T21; t++) s += u[t] * sG[n * T21 + t];
        float h = inv * s + scc[n];
        out[row * NCLS + n] = (h >= 0.f) ? h : 0.2f * h;
    }
}

// ============================================================
extern "C" void kernel_launch(void* const* d_in, const int* in_sizes, int n_in,
                              void* d_out, int out_size) {
    const float* x    = (const float*)d_in[0];
    const float* c    = (const float*)d_in[1];
    const float* b    = (const float*)d_in[2];
    const float* wei  = (const float*)d_in[3];
    const float* bais = (const float*)d_in[4];
    const float* W1   = (const float*)d_in[5];
    const float* b1   = (const float*)d_in[6];
    const float* W2   = (const float*)d_in[7];
    const float* b2   = (const float*)d_in[8];
    const float* W3   = (const float*)d_in[9];
    const float* b3   = (const float*)d_in[10];
    float* out = (float*)d_out;

    k_stage1<<<NCHUNK * COLT + 2 * WCH, 256>>>(wei, W2, W3);
    k_reduceS<<<200, 256>>>();
    k_stage3<<<MID / 8 + NCLS + 1, 256>>>(W1, W3, b2);
    k_main<<<BATCH / 256, 256>>>(x, c, b, bais, b1, b3, out);
}

// round 6
// speedup vs baseline: 4.2020x; 1.2967x over previous
#include <cuda_runtime.h>
#include <math.h>

#define N_FEAT 7
#define FUZZ   2187
#define MID    512
#define NCLS   10
#define BATCH  4096
#define T21    21
#define NCHUNK 81          // k-chunks for wei reduction
#define CHUNK_K 27         // k per chunk (81*27 = 2187)
#define COLT   9           // column tiles of 256
#define WCH    16          // j-chunks for W23 partials

// ---- device scratch (no allocations allowed) ----
__device__ float g_partialS[NCHUNK * T21 * FUZZ];  // ~14.9 MB
__device__ float g_S[T21 * FUZZ];
__device__ float g_rowS[T21];
__device__ float g_T1[T21 * MID];
__device__ float g_r1[MID];
__device__ float g_T3[NCLS * T21];
__device__ float g_r3[NCLS];
__device__ float g_c3[NCLS];
__device__ float g_partW[WCH * NCLS * MID];
__device__ float g_W23[NCLS * MID];
__device__ float g_G[NCLS * T21];
__device__ float g_q[NCLS];
__device__ float g_cc2[NCLS];

// ============================================================
// Stage 1 (R1 verbatim): partial S over k-chunks + W23 partials
// ============================================================
__global__ void k_stage1(const float* __restrict__ wei,
                         const float* __restrict__ W2,
                         const float* __restrict__ W3) {
    int b   = blockIdx.x;
    int tid = threadIdx.x;

    if (b < NCHUNK * COLT) {
        int colTile = b % COLT;
        int chunk   = b / COLT;
        int j  = colTile * 256 + tid;
        bool ok = (j < FUZZ);
        int jj = ok ? j : 0;

        float acc[T21];
#pragma unroll
        for (int t = 0; t < T21; t++) acc[t] = 0.f;

        int k0 = chunk * CHUNK_K;
#pragma unroll 3
        for (int kk = 0; kk < CHUNK_K; kk++) {
            int k = k0 + kk;
            const float* rowp = wei + (size_t)(k * 7) * FUZZ + jj;
            const int P[7] = {729, 243, 81, 27, 9, 3, 1};
#pragma unroll
            for (int f = 0; f < 7; f++) {
                float v = __ldg(rowp + f * FUZZ);
                int m = (k / P[f]) % 3;
                acc[f * 3 + 0] += (m == 0) ? v : 0.f;
                acc[f * 3 + 1] += (m == 1) ? v : 0.f;
                acc[f * 3 + 2] += (m == 2) ? v : 0.f;
            }
        }
        if (ok) {
            float* dst = g_partialS + (size_t)chunk * (T21 * FUZZ) + j;
#pragma unroll
            for (int t = 0; t < T21; t++) dst[t * FUZZ] = acc[t];
        }
    } else {
        // ---- W23 partial: W23[n,i] = sum_j W3[n,j] * W2[j,i] ----
        int b2    = b - NCHUNK * COLT;
        int itile = b2 & 1;
        int chunk = b2 >> 1;
        int i  = itile * 256 + tid;
        int j0 = chunk * 137;
        int j1 = min(FUZZ, j0 + 137);

        float acc[NCLS];
#pragma unroll
        for (int n = 0; n < NCLS; n++) acc[n] = 0.f;

        for (int j = j0; j < j1; j++) {
            float w2 = __ldg(W2 + j * MID + i);
#pragma unroll
            for (int n = 0; n < NCLS; n++)
                acc[n] += __ldg(W3 + n * FUZZ + j) * w2;
        }
#pragma unroll
        for (int n = 0; n < NCLS; n++)
            g_partW[chunk * (NCLS * MID) + n * MID + i] = acc[n];
    }
}

// ============================================================
// Stage 2 (R1 verbatim): reduce S partials (fixed order)
// ============================================================
__global__ void k_reduceS() {
    int idx = blockIdx.x * 256 + threadIdx.x;
    if (idx < T21 * FUZZ) {
        float s = 0.f;
#pragma unroll 9
        for (int c = 0; c < NCHUNK; c++)
            s += g_partialS[(size_t)c * (T21 * FUZZ) + idx];
        g_S[idx] = s;
    }
}

// ============================================================
// Stage 3 (R1 verbatim): T1 block-per-i, T3/r3/c3, rowS, W23 reduce
// ============================================================
__global__ void k_stage3(const float* __restrict__ W1,
                         const float* __restrict__ W3,
                         const float* __restrict__ b2) {
    __shared__ float sm[23 * 8];
    int b    = blockIdx.x;
    int tid  = threadIdx.x;
    int lane = tid & 31;
    int warp = tid >> 5;

    if (b < MID) {
        int i = b;
        float acc[22];
#pragma unroll
        for (int t = 0; t < 22; t++) acc[t] = 0.f;
        for (int j = tid; j < FUZZ; j += 256) {
            float w = __ldg(W1 + i * FUZZ + j);
#pragma unroll
            for (int t = 0; t < T21; t++) acc[t] += w * g_S[t * FUZZ + j];
            acc[21] += w;
        }
#pragma unroll
        for (int t = 0; t < 22; t++) {
            for (int off = 16; off; off >>= 1)
                acc[t] += __shfl_down_sync(0xffffffffu, acc[t], off);
            if (lane == 0) sm[t * 8 + warp] = acc[t];
        }
        __syncthreads();
        if (tid < 22) {
            float s = 0.f;
#pragma unroll
            for (int w = 0; w < 8; w++) s += sm[tid * 8 + w];
            if (tid < T21) g_T1[tid * MID + i] = s;
            else           g_r1[i] = s;
        }
    } else if (b < MID + NCLS) {
        int n = b - MID;
        float acc[23];
#pragma unroll
        for (int t = 0; t < 23; t++) acc[t] = 0.f;
        for (int j = tid; j < FUZZ; j += 256) {
            float w3 = __ldg(W3 + n * FUZZ + j);
#pragma unroll
            for (int t = 0; t < T21; t++) acc[t] += w3 * g_S[t * FUZZ + j];
            acc[21] += w3;
            acc[22] += w3 * __ldg(b2 + j);
        }
#pragma unroll
        for (int t = 0; t < 23; t++) {
            for (int off = 16; off; off >>= 1)
                acc[t] += __shfl_down_sync(0xffffffffu, acc[t], off);
            if (lane == 0) sm[t * 8 + warp] = acc[t];
        }
        __syncthreads();
        if (tid < 23) {
            float s = 0.f;
#pragma unroll
            for (int w = 0; w < 8; w++) s += sm[tid * 8 + w];
            if (tid < T21)       g_T3[n * T21 + tid] = s;
            else if (tid == 21)  g_r3[n] = s;
            else                 g_c3[n] = s;
        }
    } else if (b < MID + NCLS + T21) {
        int t = b - MID - NCLS;
        float s = 0.f;
        for (int j = tid; j < FUZZ; j += 256) s += g_S[t * FUZZ + j];
        for (int off = 16; off; off >>= 1)
            s += __shfl_down_sync(0xffffffffu, s, off);
        if (lane == 0) sm[warp] = s;
        __syncthreads();
        if (tid == 0) {
            float tot = 0.f;
#pragma unroll
            for (int w = 0; w < 8; w++) tot += sm[w];
            g_rowS[t] = tot;
        }
    } else {
        for (int e = tid; e < NCLS * MID; e += 256) {
            float s = 0.f;
#pragma unroll
            for (int c = 0; c < WCH; c++) s += g_partW[c * (NCLS * MID) + e];
            g_W23[e] = s;
        }
    }
}

// ============================================================
// Stage 3b (R3 verbatim): G = T3 + W23*T1^T, q, cc2 (warp per dot)
// ============================================================
__global__ void __launch_bounds__(256) k_prep(const float* __restrict__ b1,
                                              const float* __restrict__ b3) {
    int lane = threadIdx.x & 31;
    int gw   = blockIdx.x * 8 + (threadIdx.x >> 5);

    if (gw < NCLS * T21) {
        int n = gw / T21, t = gw % T21;
        float s = 0.f;
#pragma unroll
        for (int k = 0; k < MID / 32; k++) {
            int i = k * 32 + lane;
            s += g_W23[n * MID + i] * g_T1[t * MID + i];
        }
        for (int off = 16; off; off >>= 1)
            s += __shfl_down_sync(0xffffffffu, s, off);
        if (lane == 0) g_G[n * T21 + t] = s + g_T3[n * T21 + t];
    } else if (gw < NCLS * T21 + NCLS) {
        int n = gw - NCLS * T21;
        float s = 0.f;
#pragma unroll
        for (int k = 0; k < MID / 32; k++) {
            int i = k * 32 + lane;
            s += g_W23[n * MID + i] * g_r1[i];
        }
        for (int off = 16; off; off >>= 1)
            s += __shfl_down_sync(0xffffffffu, s, off);
        if (lane == 0) g_q[n] = s + g_r3[n];
    } else if (gw < NCLS * T21 + 2 * NCLS) {
        int n = gw - NCLS * T21 - NCLS;
        float s = 0.f;
#pragma unroll
        for (int k = 0; k < MID / 32; k++) {
            int i = k * 32 + lane;
            s += g_W23[n * MID + i] * __ldg(b1 + i);
        }
        for (int off = 16; off; off >>= 1)
            s += __shfl_down_sync(0xffffffffu, s, off);
        if (lane == 0) g_cc2[n] = s + g_c3[n] + __ldg(b3 + n);
    }
}

// ============================================================
// Stage 4: one thread per batch row (~250 FMA + 21 exp each)
// ============================================================
__global__ void __launch_bounds__(256) k_main(
        const float* __restrict__ x,  const float* __restrict__ cc,
        const float* __restrict__ bb, const float* __restrict__ bais,
        float* __restrict__ out) {
    __shared__ float sG[NCLS * T21];
    __shared__ float sq[NCLS];
    __shared__ float scc[NCLS];
    __shared__ float srowS[T21];
    __shared__ float sc[T21];
    __shared__ float sib[T21];

    int tid = threadIdx.x;
    for (int e = tid; e < NCLS * T21; e += 256) sG[e] = g_G[e];
    if (tid < NCLS) { sq[tid] = g_q[tid]; scc[tid] = g_cc2[tid]; }
    if (tid < T21) {
        srowS[tid] = g_rowS[tid];
        sc[tid] = __ldg(cc + tid);
        float bw = __ldg(bb + tid);
        sib[tid] = 1.0f / (bw * bw);
    }
    float bv = __ldg(bais);
    __syncthreads();

    int row = blockIdx.x * 256 + tid;
    float xv[N_FEAT];
#pragma unroll
    for (int f = 0; f < N_FEAT; f++) xv[f] = __ldg(x + row * N_FEAT + f);

    float u[T21];
    float rs = (float)FUZZ * bv;
#pragma unroll
    for (int t = 0; t < T21; t++) {
        float d = xv[t / 3] - sc[t];
        u[t] = expf(-d * d * sib[t]);
        rs += u[t] * srowS[t];
    }
    float inv = 1.0f / rs;

#pragma unroll
    for (int n = 0; n < NCLS; n++) {
        float s = bv * sq[n];
#pragma unroll
        for (int t = 0; t < T21; t++) s += u[t] * sG[n * T21 + t];
        float h = inv * s + scc[n];
        out[row * NCLS + n] = (h >= 0.f) ? h : 0.2f * h;
    }
}

// ============================================================
extern "C" void kernel_launch(void* const* d_in, const int* in_sizes, int n_in,
                              void* d_out, int out_size) {
    const float* x    = (const float*)d_in[0];
    const float* c    = (const float*)d_in[1];
    const float* b    = (const float*)d_in[2];
    const float* wei  = (const float*)d_in[3];
    const float* bais = (const float*)d_in[4];
    const float* W1   = (const float*)d_in[5];
    const float* b1   = (const float*)d_in[6];
    const float* W2   = (const float*)d_in[7];
    const float* b2   = (const float*)d_in[8];
    const float* W3   = (const float*)d_in[9];
    const float* b3   = (const float*)d_in[10];
    float* out = (float*)d_out;

    k_stage1<<<NCHUNK * COLT + 2 * WCH, 256>>>(wei, W2, W3);
    k_reduceS<<<(T21 * FUZZ + 255) / 256, 256>>>();
    k_stage3<<<MID + NCLS + T21 + 1, 256>>>(W1, W3, b2);
    k_prep<<<30, 256>>>(b1, b3);
    k_main<<<BATCH / 256, 256>>>(x, c, b, bais, out);
}

// round 7
// speedup vs baseline: 4.2790x; 1.0183x over previous
#include <cuda_runtime.h>
#include <math.h>

#define N_FEAT 7
#define FUZZ   2187
#define MID    512
#define NCLS   10
#define BATCH  4096
#define T21    21
#define NCHUNK 81          // k-chunks for wei reduction
#define CHUNK_K 27         // k per chunk (81*27 = 2187)
#define COLT   9           // column tiles of 256
#define WCH    16          // j-chunks for W23 partials

// ---- device scratch (no allocations allowed) ----
__device__ float g_partialS[NCHUNK * T21 * FUZZ];  // ~14.9 MB
__device__ float g_S[T21 * FUZZ];
__device__ float g_rowS[T21];
__device__ float g_partW[WCH * NCLS * MID];
__device__ float g_W23[NCLS * MID];
__device__ float g_partF[NCLS * COLT * 24];   // per-(n,jtile): 21 G + q + cc2a + cc2b

// ============================================================
// Stage 1 (measured-best, R1 verbatim): S partials + W23 partials
// ============================================================
__global__ void k_stage1(const float* __restrict__ wei,
                         const float* __restrict__ W2,
                         const float* __restrict__ W3) {
    int b   = blockIdx.x;
    int tid = threadIdx.x;

    if (b < NCHUNK * COLT) {
        int colTile = b % COLT;
        int chunk   = b / COLT;
        int j  = colTile * 256 + tid;
        bool ok = (j < FUZZ);
        int jj = ok ? j : 0;

        float acc[T21];
#pragma unroll
        for (int t = 0; t < T21; t++) acc[t] = 0.f;

        int k0 = chunk * CHUNK_K;
#pragma unroll 3
        for (int kk = 0; kk < CHUNK_K; kk++) {
            int k = k0 + kk;
            const float* rowp = wei + (size_t)(k * 7) * FUZZ + jj;
            const int P[7] = {729, 243, 81, 27, 9, 3, 1};
#pragma unroll
            for (int f = 0; f < 7; f++) {
                float v = __ldg(rowp + f * FUZZ);
                int m = (k / P[f]) % 3;
                acc[f * 3 + 0] += (m == 0) ? v : 0.f;
                acc[f * 3 + 1] += (m == 1) ? v : 0.f;
                acc[f * 3 + 2] += (m == 2) ? v : 0.f;
            }
        }
        if (ok) {
            float* dst = g_partialS + (size_t)chunk * (T21 * FUZZ) + j;
#pragma unroll
            for (int t = 0; t < T21; t++) dst[t * FUZZ] = acc[t];
        }
    } else {
        // ---- W23 partial: W23[n,i] = sum_j W3[n,j] * W2[j,i] ----
        int b2    = b - NCHUNK * COLT;
        int itile = b2 & 1;
        int chunk = b2 >> 1;
        int i  = itile * 256 + tid;
        int j0 = chunk * 137;
        int j1 = min(FUZZ, j0 + 137);

        float acc[NCLS];
#pragma unroll
        for (int n = 0; n < NCLS; n++) acc[n] = 0.f;

        for (int j = j0; j < j1; j++) {
            float w2 = __ldg(W2 + j * MID + i);
#pragma unroll
            for (int n = 0; n < NCLS; n++)
                acc[n] += __ldg(W3 + n * FUZZ + j) * w2;
        }
#pragma unroll
        for (int n = 0; n < NCLS; n++)
            g_partW[chunk * (NCLS * MID) + n * MID + i] = acc[n];
    }
}

// ============================================================
// Stage 2: reduce S partials (R1 verbatim) + finalize W23
// ============================================================
__global__ void k_reduceS() {
    int b = blockIdx.x, tid = threadIdx.x;
    if (b < 180) {
        int idx = b * 256 + tid;
        if (idx < T21 * FUZZ) {
            float s = 0.f;
#pragma unroll 9
            for (int c = 0; c < NCHUNK; c++)
                s += g_partialS[(size_t)c * (T21 * FUZZ) + idx];
            g_S[idx] = s;
        }
    } else {
        int e = (b - 180) * 256 + tid;   // 0..5119
        if (e < NCLS * MID) {
            float s = 0.f;
#pragma unroll
            for (int c = 0; c < WCH; c++) s += g_partW[c * (NCLS * MID) + e];
            g_W23[e] = s;
        }
    }
}

// ============================================================
// Stage 3: fold.  V[n,j] = W3[n,j] + sum_i W23[n,i] W1[i,j]
//   per (n, j-tile of 256): partial G[t] = sum_j V*S[t,j], q = sum_j V,
//   cc2a = sum_j W3[n,j] b2[j], cc2b (jt==0) = b3[n] + sum_i W23[n,i] b1[i]
//   blocks 90..110: rowS[t]
// ============================================================
__global__ void __launch_bounds__(256) k_fold(const float* __restrict__ W1,
                                              const float* __restrict__ W3,
                                              const float* __restrict__ b1,
                                              const float* __restrict__ b2,
                                              const float* __restrict__ b3) {
    int b = blockIdx.x, tid = threadIdx.x, lane = tid & 31, warp = tid >> 5;

    if (b < NCLS * COLT) {
        __shared__ float sW[MID];
        __shared__ float sV[256];
        int n = b / COLT, jt = b % COLT;

        for (int i = tid; i < MID; i += 256) sW[i] = g_W23[n * MID + i];
        __syncthreads();

        int j = jt * 256 + tid;
        bool jok = (j < FUZZ);
        int jj = jok ? j : (FUZZ - 1);

        float V = __ldg(W3 + n * FUZZ + jj);
        const float* wp = W1 + jj;
#pragma unroll 8
        for (int i = 0; i < MID; i++)
            V += sW[i] * __ldg(wp + (size_t)i * FUZZ);
        sV[tid] = jok ? V : 0.f;
        __syncthreads();

        float* dst = g_partF + (n * COLT + jt) * 24;
        int j0 = jt * 256;
        for (int t = warp; t < 24; t += 8) {
            float s = 0.f;
            if (t < T21) {
#pragma unroll
                for (int c = 0; c < 8; c++) {
                    int idx = c * 32 + lane;
                    int jx = j0 + idx;
                    float Sv = (jx < FUZZ) ? __ldg(&g_S[t * FUZZ + jx]) : 0.f;
                    s += sV[idx] * Sv;
                }
            } else if (t == 21) {
#pragma unroll
                for (int c = 0; c < 8; c++) s += sV[c * 32 + lane];
            } else if (t == 22) {
#pragma unroll
                for (int c = 0; c < 8; c++) {
                    int jx = j0 + c * 32 + lane;
                    if (jx < FUZZ)
                        s += __ldg(W3 + n * FUZZ + jx) * __ldg(b2 + jx);
                }
            } else { // t == 23: only jt==0 contributes b3 + W23.b1
                if (jt == 0) {
#pragma unroll
                    for (int c = 0; c < MID / 32; c++)
                        s += sW[c * 32 + lane] * __ldg(b1 + c * 32 + lane);
                }
            }
            for (int o = 16; o; o >>= 1)
                s += __shfl_down_sync(0xffffffffu, s, o);
            if (lane == 0) {
                if (t == 23 && jt == 0) s += __ldg(b3 + n);
                dst[t] = s;
            }
        }
    } else {
        // rowS[t] = sum_j S[t,j]
        __shared__ float sred[8];
        int t = b - NCLS * COLT;
        float s = 0.f;
        for (int j = tid; j < FUZZ; j += 256) s += g_S[t * FUZZ + j];
        for (int o = 16; o; o >>= 1)
            s += __shfl_down_sync(0xffffffffu, s, o);
        if (lane == 0) sred[warp] = s;
        __syncthreads();
        if (tid == 0) {
            float tot = 0.f;
#pragma unroll
            for (int w = 0; w < 8; w++) tot += sred[w];
            g_rowS[t] = tot;
        }
    }
}

// ============================================================
// Stage 4: assemble partials, then one thread per batch row
// ============================================================
__global__ void __launch_bounds__(256) k_main(
        const float* __restrict__ x,  const float* __restrict__ cc,
        const float* __restrict__ bb, const float* __restrict__ bais,
        float* __restrict__ out) {
    __shared__ float sG[NCLS * T21];
    __shared__ float sq[NCLS];
    __shared__ float scc[NCLS];
    __shared__ float srowS[T21];
    __shared__ float sc[T21];
    __shared__ float sib[T21];

    int tid = threadIdx.x;
    for (int e = tid; e < NCLS * T21; e += 256) {
        int n = e / T21, t = e % T21;
        float s = 0.f;
#pragma unroll
        for (int jt = 0; jt < COLT; jt++)
            s += g_partF[(n * COLT + jt) * 24 + t];
        sG[e] = s;
    }
    if (tid < NCLS) {
        float qq = 0.f, cv = 0.f;
#pragma unroll
        for (int jt = 0; jt < COLT; jt++) {
            qq += g_partF[(tid * COLT + jt) * 24 + 21];
            cv += g_partF[(tid * COLT + jt) * 24 + 22]
                + g_partF[(tid * COLT + jt) * 24 + 23];
        }
        sq[tid] = qq;
        scc[tid] = cv;
    }
    if (tid < T21) {
        srowS[tid] = g_rowS[tid];
        sc[tid] = __ldg(cc + tid);
        float bw = __ldg(bb + tid);
        sib[tid] = 1.0f / (bw * bw);
    }
    float bv = __ldg(bais);
    __syncthreads();

    int row = blockIdx.x * 256 + tid;
    float xv[N_FEAT];
#pragma unroll
    for (int f = 0; f < N_FEAT; f++) xv[f] = __ldg(x + row * N_FEAT + f);

    float u[T21];
    float rs = (float)FUZZ * bv;
#pragma unroll
    for (int t = 0; t < T21; t++) {
        float d = xv[t / 3] - sc[t];
        u[t] = expf(-d * d * sib[t]);
        rs += u[t] * srowS[t];
    }
    float inv = 1.0f / rs;

#pragma unroll
    for (int n = 0; n < NCLS; n++) {
        float s = bv * sq[n];
#pragma unroll
        for (int t = 0; t < T21; t++) s += u[t] * sG[n * T21 + t];
        float h = inv * s + scc[n];
        out[row * NCLS + n] = (h >= 0.f) ? h : 0.2f * h;
    }
}

// ============================================================
extern "C" void kernel_launch(void* const* d_in, const int* in_sizes, int n_in,
                              void* d_out, int out_size) {
    const float* x    = (const float*)d_in[0];
    const float* c    = (const float*)d_in[1];
    const float* b    = (const float*)d_in[2];
    const float* wei  = (const float*)d_in[3];
    const float* bais = (const float*)d_in[4];
    const float* W1   = (const float*)d_in[5];
    const float* b1   = (const float*)d_in[6];
    const float* W2   = (const float*)d_in[7];
    const float* b2   = (const float*)d_in[8];
    const float* W3   = (const float*)d_in[9];
    const float* b3   = (const float*)d_in[10];
    float* out = (float*)d_out;

    k_stage1<<<NCHUNK * COLT + 2 * WCH, 256>>>(wei, W2, W3);
    k_reduceS<<<200, 256>>>();
    k_fold<<<NCLS * COLT + T21, 256>>>(W1, W3, b1, b2, b3);
    k_main<<<BATCH / 256, 256>>>(x, c, b, bais, out);
}